// round 4
// baseline (speedup 1.0000x reference)
#include <cuda_runtime.h>

#define C 16
#define HEADS 2
#define HD 8
#define WS 8
#define HID 64
#define HH 512
#define WW 512
#define NTOK 64

typedef unsigned long long u64;

__device__ __forceinline__ u64 pack2(float a, float b) {
    u64 r; asm("mov.b64 %0, {%1,%2};" : "=l"(r) : "f"(a), "f"(b)); return r;
}
__device__ __forceinline__ void unpack2(u64 v, float& a, float& b) {
    asm("mov.b64 {%0,%1}, %2;" : "=f"(a), "=f"(b) : "l"(v));
}
__device__ __forceinline__ void ffma2(u64& d, u64 a, u64 b) {
    asm("fma.rn.f32x2 %0, %1, %2, %0;" : "+l"(d) : "l"(a), "l"(b));
}
__device__ __forceinline__ float fexp(float x) {
    float r; asm("ex2.approx.f32 %0, %1;" : "=f"(r) : "f"(x * 1.4426950408889634f)); return r;
}
__device__ __forceinline__ float ftanh(float x) {
    float r; asm("tanh.approx.f32 %0, %1;" : "=f"(r) : "f"(x)); return r;
}

// dot of 16 fp32: a = 8 packed pairs (regs), w = shared ptr (8B aligned)
__device__ __forceinline__ float dot16(const u64* a, const float* w) {
    const u64* wp = reinterpret_cast<const u64*>(w);
    u64 acc = 0ull;
#pragma unroll
    for (int i = 0; i < 8; i++) ffma2(acc, a[i], wp[i]);
    float lo, hi; unpack2(acc, lo, hi); return lo + hi;
}
__device__ __forceinline__ float dot8(const u64* a, const float* w) {
    const u64* wp = reinterpret_cast<const u64*>(w);
    u64 acc = 0ull;
#pragma unroll
    for (int i = 0; i < 4; i++) ffma2(acc, a[i], wp[i]);
    float lo, hi; unpack2(acc, lo, hi); return lo + hi;
}

__global__ __launch_bounds__(64) void swin_fused_kernel(
    const float* __restrict__ x,
    const float* __restrict__ pos_w, const float* __restrict__ pos_b,
    const float* __restrict__ alpha1, const float* __restrict__ beta1, const float* __restrict__ color1,
    const float* __restrict__ qkv_w, const float* __restrict__ qkv_b,
    const float* __restrict__ proj_w, const float* __restrict__ proj_b,
    const float* __restrict__ alpha2, const float* __restrict__ beta2, const float* __restrict__ color2,
    const float* __restrict__ fc1_w, const float* __restrict__ fc1_b,
    const float* __restrict__ fc2_w, const float* __restrict__ fc2_b,
    float* __restrict__ out)
{
    __shared__ __align__(16) float sh_halo[C][10][10];
    __shared__ __align__(16) float sh_k[HEADS][NTOK][HD];
    __shared__ __align__(16) float sh_v[HEADS][NTOK][HD];
    __shared__ __align__(16) float sh_color1[C * C];
    __shared__ __align__(16) float sh_qkvw[48 * C];
    __shared__ __align__(16) float sh_projw[C * C];
    __shared__ __align__(16) float sh_color2[C * C];
    __shared__ __align__(16) float sh_fc1w[HID * C];
    __shared__ __align__(16) float sh_fc2wt[HID * C];   // transposed: [j][c2]
    __shared__ __align__(16) float sh_posw[C * 9];
    __shared__ float sh_posb[C], sh_a1[C], sh_b1[C], sh_qkvb[48];
    __shared__ float sh_projb[C], sh_a2[C], sh_b2[C], sh_fc1b[HID], sh_fc2b[C];

    const int tid = threadIdx.x;
    const int b  = blockIdx.z;
    const int wy = blockIdx.y, wx = blockIdx.x;
    const int y0 = wy * WS, x0 = wx * WS;

    // ---- cooperative weight loads (hot in L2 across 16384 CTAs) ----
    for (int i = tid; i < C * C; i += 64) {
        sh_color1[i] = color1[i];
        sh_projw[i]  = proj_w[i];
        sh_color2[i] = color2[i];
    }
    for (int i = tid; i < 48 * C; i += 64) sh_qkvw[i] = qkv_w[i];
    for (int i = tid; i < HID * C; i += 64) {
        sh_fc1w[i] = fc1_w[i];
        int c2 = i >> 6, j = i & 63;            // fc2_w layout [C][HID]
        sh_fc2wt[j * C + c2] = fc2_w[i];
    }
    for (int i = tid; i < C * 9; i += 64) sh_posw[i] = pos_w[i];
    if (tid < C) {
        sh_posb[tid] = pos_b[tid];
        sh_a1[tid] = alpha1[tid]; sh_b1[tid] = beta1[tid];
        sh_projb[tid] = proj_b[tid];
        sh_a2[tid] = alpha2[tid]; sh_b2[tid] = beta2[tid];
        sh_fc2b[tid] = fc2_b[tid];
    }
    if (tid < 48) sh_qkvb[tid] = qkv_b[tid];
    sh_fc1b[tid] = fc1_b[tid];                  // HID == 64 == blockDim

    // ---- halo load: [C][10][10] with zero padding ----
    const float* xb = x + (size_t)b * C * HH * WW;
    for (int i = tid; i < C * 100; i += 64) {
        int c = i / 100, rem = i - c * 100;
        int r = rem / 10, cc = rem - r * 10;
        int gy = y0 - 1 + r, gx = x0 - 1 + cc;
        float v = 0.f;
        if ((unsigned)gy < HH && (unsigned)gx < WW)
            v = xb[c * (HH * WW) + gy * WW + gx];
        sh_halo[c][r][cc] = v;
    }
    __syncthreads();

    const int ty = tid >> 3, tx = tid & 7;

    // ---- depthwise 3x3 conv + residual + bias -> shortcut s[C] (exact fp32) ----
    float s[C];
#pragma unroll
    for (int c = 0; c < C; c++) {
        float acc = sh_halo[c][ty + 1][tx + 1] + sh_posb[c];
#pragma unroll
        for (int di = 0; di < 3; di++)
#pragma unroll
            for (int dj = 0; dj < 3; dj++)
                acc = fmaf(sh_halo[c][ty + di][tx + dj], sh_posw[c * 9 + di * 3 + dj], acc);
        s[c] = acc;
    }

    // ---- aff1 ----
    u64 sp[8];
#pragma unroll
    for (int i = 0; i < 8; i++) sp[i] = pack2(s[2 * i], s[2 * i + 1]);
    float yv[C];
#pragma unroll
    for (int j = 0; j < C; j++)
        yv[j] = fmaf(dot16(sp, &sh_color1[j * C]), sh_a1[j], sh_b1[j]);

    // ---- qkv projection ----
    u64 yp[8];
#pragma unroll
    for (int i = 0; i < 8; i++) yp[i] = pack2(yv[2 * i], yv[2 * i + 1]);
    float q[C];
#pragma unroll
    for (int j = 0; j < C; j++)
        q[j] = (dot16(yp, &sh_qkvw[j * C]) + sh_qkvb[j]) * 0.35355339059327373f;  // hd^-0.5
#pragma unroll
    for (int j = 0; j < C; j++)
        sh_k[j >> 3][tid][j & 7] = dot16(yp, &sh_qkvw[(16 + j) * C]) + sh_qkvb[16 + j];
#pragma unroll
    for (int j = 0; j < C; j++)
        sh_v[j >> 3][tid][j & 7] = dot16(yp, &sh_qkvw[(32 + j) * C]) + sh_qkvb[32 + j];
    __syncthreads();

    // ---- window attention (each thread = one query token) ----
    float ao[C];
#pragma unroll
    for (int h = 0; h < HEADS; h++) {
        u64 qp[4];
#pragma unroll
        for (int i = 0; i < 4; i++) qp[i] = pack2(q[h * 8 + 2 * i], q[h * 8 + 2 * i + 1]);

        float logits[NTOK];
        float mx = -1e30f;
#pragma unroll
        for (int m = 0; m < NTOK; m++) {
            float l = dot8(qp, &sh_k[h][m][0]);
            logits[m] = l;
            mx = fmaxf(mx, l);
        }
        float ssum = 0.f;
        u64 oacc[4] = {0ull, 0ull, 0ull, 0ull};
#pragma unroll
        for (int m = 0; m < NTOK; m++) {
            float p = fexp(logits[m] - mx);
            ssum += p;
            u64 pp = pack2(p, p);
            const u64* vp = reinterpret_cast<const u64*>(&sh_v[h][m][0]);
#pragma unroll
            for (int i = 0; i < 4; i++) ffma2(oacc[i], pp, vp[i]);
        }
        float rinv = 1.0f / ssum;
#pragma unroll
        for (int i = 0; i < 4; i++) {
            float lo, hi; unpack2(oacc[i], lo, hi);
            ao[h * 8 + 2 * i]     = lo * rinv;
            ao[h * 8 + 2 * i + 1] = hi * rinv;
        }
    }

    // ---- proj + residual ----
    u64 aop[8];
#pragma unroll
    for (int i = 0; i < 8; i++) aop[i] = pack2(ao[2 * i], ao[2 * i + 1]);
    float x2[C];
#pragma unroll
    for (int j = 0; j < C; j++)
        x2[j] = s[j] + dot16(aop, &sh_projw[j * C]) + sh_projb[j];

    // ---- aff2 ----
    u64 x2p[8];
#pragma unroll
    for (int i = 0; i < 8; i++) x2p[i] = pack2(x2[2 * i], x2[2 * i + 1]);
    float a2[C];
#pragma unroll
    for (int j = 0; j < C; j++)
        a2[j] = fmaf(dot16(x2p, &sh_color2[j * C]), sh_a2[j], sh_b2[j]);

    // ---- MLP: fc1 -> GELU -> fc2 (fused, h1 never stored) ----
    u64 a2p[8];
#pragma unroll
    for (int i = 0; i < 8; i++) a2p[i] = pack2(a2[2 * i], a2[2 * i + 1]);
    u64 fo[8] = {0ull, 0ull, 0ull, 0ull, 0ull, 0ull, 0ull, 0ull};
#pragma unroll
    for (int j = 0; j < HID; j++) {
        float t = dot16(a2p, &sh_fc1w[j * C]) + sh_fc1b[j];
        float u = 0.7978845608028654f * fmaf(0.044715f * t, t * t, t);
        float g = 0.5f * t * (1.f + ftanh(u));
        u64 gg = pack2(g, g);
        const u64* wp = reinterpret_cast<const u64*>(&sh_fc2wt[j * C]);
#pragma unroll
        for (int i = 0; i < 8; i++) ffma2(fo[i], gg, wp[i]);
    }

    // ---- residual + write out in NCHW ----
    float* ob = out + (size_t)b * C * HH * WW;
    const int gy = y0 + ty, gx = x0 + tx;
#pragma unroll
    for (int i = 0; i < 8; i++) {
        float lo, hi; unpack2(fo[i], lo, hi);
        int c0 = 2 * i;
        ob[c0 * (HH * WW) + gy * WW + gx]       = x2[c0]     + sh_fc2b[c0]     + lo;
        ob[(c0 + 1) * (HH * WW) + gy * WW + gx] = x2[c0 + 1] + sh_fc2b[c0 + 1] + hi;
    }
}

extern "C" void kernel_launch(void* const* d_in, const int* in_sizes, int n_in,
                              void* d_out, int out_size) {
    (void)n_in; (void)out_size;
    const float* x      = (const float*)d_in[0];
    const float* pos_w  = (const float*)d_in[1];
    const float* pos_b  = (const float*)d_in[2];
    const float* alpha1 = (const float*)d_in[3];
    const float* beta1  = (const float*)d_in[4];
    const float* color1 = (const float*)d_in[5];
    const float* qkv_w  = (const float*)d_in[6];
    const float* qkv_b  = (const float*)d_in[7];
    const float* proj_w = (const float*)d_in[8];
    const float* proj_b = (const float*)d_in[9];
    const float* alpha2 = (const float*)d_in[10];
    const float* beta2  = (const float*)d_in[11];
    const float* color2 = (const float*)d_in[12];
    const float* fc1_w  = (const float*)d_in[13];
    const float* fc1_b  = (const float*)d_in[14];
    const float* fc2_w  = (const float*)d_in[15];
    const float* fc2_b  = (const float*)d_in[16];

    int B = in_sizes[0] / (C * HH * WW);
    dim3 grid(WW / WS, HH / WS, B);
    swin_fused_kernel<<<grid, 64>>>(
        x, pos_w, pos_b, alpha1, beta1, color1, qkv_w, qkv_b,
        proj_w, proj_b, alpha2, beta2, color2, fc1_w, fc1_b, fc2_w, fc2_b,
        (float*)d_out);
}

// round 5
// speedup vs baseline: 1.3119x; 1.3119x over previous
#include <cuda_runtime.h>

#define C 16
#define HEADS 2
#define HD 8
#define WS 8
#define HID 64
#define HH 512
#define WW 512
#define NTOK 64

typedef unsigned long long u64;

__device__ __forceinline__ u64 pack2(float a, float b) {
    u64 r; asm("mov.b64 %0, {%1,%2};" : "=l"(r) : "f"(a), "f"(b)); return r;
}
__device__ __forceinline__ void unpack2(u64 v, float& a, float& b) {
    asm("mov.b64 {%0,%1}, %2;" : "=f"(a), "=f"(b) : "l"(v));
}
__device__ __forceinline__ void ffma2(u64& d, u64 a, u64 b) {
    asm("fma.rn.f32x2 %0, %1, %2, %0;" : "+l"(d) : "l"(a), "l"(b));
}
__device__ __forceinline__ float fexp(float x) {
    float r; asm("ex2.approx.f32 %0, %1;" : "=f"(r) : "f"(x * 1.4426950408889634f)); return r;
}
__device__ __forceinline__ float ftanh(float x) {
    float r; asm("tanh.approx.f32 %0, %1;" : "=f"(r) : "f"(x)); return r;
}
__device__ __forceinline__ float hsum2(u64 a, u64 b) {
    float x0, x1, y0, y1; unpack2(a, x0, x1); unpack2(b, y0, y1);
    return (x0 + x1) + (y0 + y1);
}

// 16-wide dot for TWO tokens sharing one weight row (4x LDS.128, 16 ffma2)
__device__ __forceinline__ void dot16x2(const u64* a0, const u64* a1,
                                        const float* w, float& r0, float& r1) {
    const ulonglong2* wp = reinterpret_cast<const ulonglong2*>(w);
    ulonglong2 w0 = wp[0], w1 = wp[1], w2 = wp[2], w3 = wp[3];
    u64 p0 = 0, q0 = 0, p1 = 0, q1 = 0;
    ffma2(p0, a0[0], w0.x); ffma2(q0, a0[1], w0.y);
    ffma2(p0, a0[2], w1.x); ffma2(q0, a0[3], w1.y);
    ffma2(p0, a0[4], w2.x); ffma2(q0, a0[5], w2.y);
    ffma2(p0, a0[6], w3.x); ffma2(q0, a0[7], w3.y);
    ffma2(p1, a1[0], w0.x); ffma2(q1, a1[1], w0.y);
    ffma2(p1, a1[2], w1.x); ffma2(q1, a1[3], w1.y);
    ffma2(p1, a1[4], w2.x); ffma2(q1, a1[5], w2.y);
    ffma2(p1, a1[6], w3.x); ffma2(q1, a1[7], w3.y);
    r0 = hsum2(p0, q0); r1 = hsum2(p1, q1);
}

__global__ __launch_bounds__(64) void swin_fused_kernel(
    const float* __restrict__ x,
    const float* __restrict__ pos_w, const float* __restrict__ pos_b,
    const float* __restrict__ alpha1, const float* __restrict__ beta1, const float* __restrict__ color1,
    const float* __restrict__ qkv_w, const float* __restrict__ qkv_b,
    const float* __restrict__ proj_w, const float* __restrict__ proj_b,
    const float* __restrict__ alpha2, const float* __restrict__ beta2, const float* __restrict__ color2,
    const float* __restrict__ fc1_w, const float* __restrict__ fc1_b,
    const float* __restrict__ fc2_w, const float* __restrict__ fc2_b,
    float* __restrict__ out)
{
    // union buffer: halo [16][10][18] (2880 floats) THEN k/v [2][2][64][8] each
    __shared__ __align__(16) float sh_dyn[4096];
    __shared__ __align__(16) float sh_color1[C * C];
    __shared__ __align__(16) float sh_qkvw[48 * C];
    __shared__ __align__(16) float sh_projw[C * C];
    __shared__ __align__(16) float sh_color2[C * C];
    __shared__ __align__(16) float sh_fc1w[HID * C];
    __shared__ __align__(16) float sh_fc2wt[HID * C];   // transposed [j][c2]
    __shared__ __align__(16) float sh_posw[C * 9];
    __shared__ float sh_posb[C], sh_a1[C], sh_b1[C], sh_qkvb[48];
    __shared__ float sh_projb[C], sh_a2[C], sh_b2[C], sh_fc1b[HID], sh_fc2b[C];

    const int tid = threadIdx.x;
    const int b  = blockIdx.z;
    const int y0 = blockIdx.y * WS;
    const int x0 = blockIdx.x * (2 * WS);    // CTA covers 2 horizontal windows

    // ---- cooperative weight loads ----
    for (int i = tid; i < C * C; i += 64) {
        sh_color1[i] = color1[i];
        sh_projw[i]  = proj_w[i];
        sh_color2[i] = color2[i];
    }
    for (int i = tid; i < 48 * C; i += 64) sh_qkvw[i] = qkv_w[i];
    for (int i = tid; i < HID * C; i += 64) {
        sh_fc1w[i] = fc1_w[i];
        int c2 = i >> 6, j = i & 63;
        sh_fc2wt[j * C + c2] = fc2_w[i];
    }
    for (int i = tid; i < C * 9; i += 64) sh_posw[i] = pos_w[i];
    if (tid < C) {
        sh_posb[tid] = pos_b[tid];
        sh_a1[tid] = alpha1[tid]; sh_b1[tid] = beta1[tid];
        sh_projb[tid] = proj_b[tid];
        sh_a2[tid] = alpha2[tid]; sh_b2[tid] = beta2[tid];
        sh_fc2b[tid] = fc2_b[tid];
    }
    if (tid < 48) sh_qkvb[tid] = qkv_b[tid];
    sh_fc1b[tid] = fc1_b[tid];

    // ---- halo load: [C][10][18] with zero padding ----
    const float* xb = x + (size_t)b * C * HH * WW;
#define HALO(c, r, cc) sh_dyn[(c) * 180 + (r) * 18 + (cc)]
    for (int i = tid; i < C * 180; i += 64) {
        int c = i / 180, rem = i - c * 180;
        int r = rem / 18, cc = rem - r * 18;
        int gy = y0 - 1 + r, gx = x0 - 1 + cc;
        float v = 0.f;
        if ((unsigned)gy < HH && (unsigned)gx < WW)
            v = xb[c * (HH * WW) + gy * WW + gx];
        sh_dyn[i] = v;
    }
    __syncthreads();

    // thread t: window w = t>>5; owns tokens (ty0,tx) and (ty0+4,tx) of window w
    const int w = tid >> 5, lane = tid & 31;
    const int ty0 = lane >> 3, tx = lane & 7;
    const int hc = w * 8 + tx;   // halo col base (tap dj -> col hc+dj; center hc+1)

    // ---- depthwise 3x3 conv + residual + bias (exact fp32 shortcut) ----
    float s0[C], s1[C];
#pragma unroll
    for (int c = 0; c < C; c++) {
        float a0 = HALO(c, ty0 + 1, hc + 1) + sh_posb[c];
        float a1 = HALO(c, ty0 + 5, hc + 1) + sh_posb[c];
#pragma unroll
        for (int di = 0; di < 3; di++)
#pragma unroll
            for (int dj = 0; dj < 3; dj++) {
                float wgt = sh_posw[c * 9 + di * 3 + dj];
                a0 = fmaf(HALO(c, ty0 + di,     hc + dj), wgt, a0);
                a1 = fmaf(HALO(c, ty0 + 4 + di, hc + dj), wgt, a1);
            }
        s0[c] = a0; s1[c] = a1;
    }
    __syncthreads();   // all halo reads done -> sh_dyn reusable as K/V

    float* sh_k = sh_dyn;          // [(w*2+h)*64 + m] * 8
    float* sh_v = sh_dyn + 2048;

    u64 sp0[8], sp1[8];
#pragma unroll
    for (int i = 0; i < 8; i++) {
        sp0[i] = pack2(s0[2 * i], s0[2 * i + 1]);
        sp1[i] = pack2(s1[2 * i], s1[2 * i + 1]);
    }

    // ---- aff1 ----
    u64 yp0[8], yp1[8];
#pragma unroll
    for (int j = 0; j < C; j += 2) {
        float ra0, ra1, rb0, rb1;
        dot16x2(sp0, sp1, &sh_color1[j * C], ra0, ra1);
        dot16x2(sp0, sp1, &sh_color1[(j + 1) * C], rb0, rb1);
        yp0[j >> 1] = pack2(fmaf(ra0, sh_a1[j], sh_b1[j]), fmaf(rb0, sh_a1[j + 1], sh_b1[j + 1]));
        yp1[j >> 1] = pack2(fmaf(ra1, sh_a1[j], sh_b1[j]), fmaf(rb1, sh_a1[j + 1], sh_b1[j + 1]));
    }

    // ---- qkv ----
    const float SCL = 0.35355339059327373f;   // hd^-0.5
    u64 qp0[2][4], qp1[2][4];
#pragma unroll
    for (int j = 0; j < C; j += 2) {
        float ra0, ra1, rb0, rb1;
        dot16x2(yp0, yp1, &sh_qkvw[j * C], ra0, ra1);
        dot16x2(yp0, yp1, &sh_qkvw[(j + 1) * C], rb0, rb1);
        ra0 = (ra0 + sh_qkvb[j]) * SCL;     rb0 = (rb0 + sh_qkvb[j + 1]) * SCL;
        ra1 = (ra1 + sh_qkvb[j]) * SCL;     rb1 = (rb1 + sh_qkvb[j + 1]) * SCL;
        qp0[j >> 3][(j & 7) >> 1] = pack2(ra0, rb0);
        qp1[j >> 3][(j & 7) >> 1] = pack2(ra1, rb1);
    }
    {
        float k0f[C], k1f[C];
#pragma unroll
        for (int j = 0; j < C; j++)
            dot16x2(yp0, yp1, &sh_qkvw[(16 + j) * C], k0f[j], k1f[j]);
#pragma unroll
        for (int j = 0; j < C; j++) { k0f[j] += sh_qkvb[16 + j]; k1f[j] += sh_qkvb[16 + j]; }
#pragma unroll
        for (int h = 0; h < HEADS; h++) {
            float* kr0 = &sh_k[((w * 2 + h) * 64 + lane) * 8];
            float* kr1 = &sh_k[((w * 2 + h) * 64 + lane + 32) * 8];
            *(float4*)(kr0)     = make_float4(k0f[h * 8 + 0], k0f[h * 8 + 1], k0f[h * 8 + 2], k0f[h * 8 + 3]);
            *(float4*)(kr0 + 4) = make_float4(k0f[h * 8 + 4], k0f[h * 8 + 5], k0f[h * 8 + 6], k0f[h * 8 + 7]);
            *(float4*)(kr1)     = make_float4(k1f[h * 8 + 0], k1f[h * 8 + 1], k1f[h * 8 + 2], k1f[h * 8 + 3]);
            *(float4*)(kr1 + 4) = make_float4(k1f[h * 8 + 4], k1f[h * 8 + 5], k1f[h * 8 + 6], k1f[h * 8 + 7]);
        }
#pragma unroll
        for (int j = 0; j < C; j++)
            dot16x2(yp0, yp1, &sh_qkvw[(32 + j) * C], k0f[j], k1f[j]);
#pragma unroll
        for (int j = 0; j < C; j++) { k0f[j] += sh_qkvb[32 + j]; k1f[j] += sh_qkvb[32 + j]; }
#pragma unroll
        for (int h = 0; h < HEADS; h++) {
            float* vr0 = &sh_v[((w * 2 + h) * 64 + lane) * 8];
            float* vr1 = &sh_v[((w * 2 + h) * 64 + lane + 32) * 8];
            *(float4*)(vr0)     = make_float4(k0f[h * 8 + 0], k0f[h * 8 + 1], k0f[h * 8 + 2], k0f[h * 8 + 3]);
            *(float4*)(vr0 + 4) = make_float4(k0f[h * 8 + 4], k0f[h * 8 + 5], k0f[h * 8 + 6], k0f[h * 8 + 7]);
            *(float4*)(vr1)     = make_float4(k1f[h * 8 + 0], k1f[h * 8 + 1], k1f[h * 8 + 2], k1f[h * 8 + 3]);
            *(float4*)(vr1 + 4) = make_float4(k1f[h * 8 + 4], k1f[h * 8 + 5], k1f[h * 8 + 6], k1f[h * 8 + 7]);
        }
    }
    __syncwarp();   // K/V are warp-private (warp == window)

    // ---- window attention, no-max online softmax (logits ~ +-0.1) ----
    u64 aop0[8], aop1[8];
#pragma unroll
    for (int h = 0; h < HEADS; h++) {
        const ulonglong2* kb = (const ulonglong2*)&sh_k[(w * 2 + h) * 64 * 8];
        const ulonglong2* vb = (const ulonglong2*)&sh_v[(w * 2 + h) * 64 * 8];
        float sum0 = 0.f, sum1 = 0.f;
        u64 o0[4] = {0, 0, 0, 0}, o1[4] = {0, 0, 0, 0};
#pragma unroll 4
        for (int m = 0; m < NTOK; m++) {
            ulonglong2 ka = kb[2 * m], kc = kb[2 * m + 1];
            u64 d0a = 0, d0b = 0, d1a = 0, d1b = 0;
            ffma2(d0a, qp0[h][0], ka.x); ffma2(d0b, qp0[h][1], ka.y);
            ffma2(d0a, qp0[h][2], kc.x); ffma2(d0b, qp0[h][3], kc.y);
            ffma2(d1a, qp1[h][0], ka.x); ffma2(d1b, qp1[h][1], ka.y);
            ffma2(d1a, qp1[h][2], kc.x); ffma2(d1b, qp1[h][3], kc.y);
            float p0 = fexp(hsum2(d0a, d0b));
            float p1 = fexp(hsum2(d1a, d1b));
            sum0 += p0; sum1 += p1;
            ulonglong2 va = vb[2 * m], vc = vb[2 * m + 1];
            u64 pp0 = pack2(p0, p0), pp1 = pack2(p1, p1);
            ffma2(o0[0], pp0, va.x); ffma2(o0[1], pp0, va.y);
            ffma2(o0[2], pp0, vc.x); ffma2(o0[3], pp0, vc.y);
            ffma2(o1[0], pp1, va.x); ffma2(o1[1], pp1, va.y);
            ffma2(o1[2], pp1, vc.x); ffma2(o1[3], pp1, vc.y);
        }
        float r0 = 1.0f / sum0, r1 = 1.0f / sum1;
        u64 rr0 = pack2(r0, r0), rr1 = pack2(r1, r1);
#pragma unroll
        for (int i = 0; i < 4; i++) {
            u64 t0 = 0, t1 = 0;
            ffma2(t0, o0[i], rr0);
            ffma2(t1, o1[i], rr1);
            aop0[h * 4 + i] = t0;
            aop1[h * 4 + i] = t1;
        }
    }

    // ---- proj + residual ----
    u64 x2p0[8], x2p1[8];
#pragma unroll
    for (int j = 0; j < C; j += 2) {
        float ra0, ra1, rb0, rb1;
        dot16x2(aop0, aop1, &sh_projw[j * C], ra0, ra1);
        dot16x2(aop0, aop1, &sh_projw[(j + 1) * C], rb0, rb1);
        float sa0, sa1, sb0, sb1;
        unpack2(sp0[j >> 1], sa0, sb0);
        unpack2(sp1[j >> 1], sa1, sb1);
        x2p0[j >> 1] = pack2(sa0 + ra0 + sh_projb[j], sb0 + rb0 + sh_projb[j + 1]);
        x2p1[j >> 1] = pack2(sa1 + ra1 + sh_projb[j], sb1 + rb1 + sh_projb[j + 1]);
    }

    // ---- aff2 ----
    u64 a2p0[8], a2p1[8];
#pragma unroll
    for (int j = 0; j < C; j += 2) {
        float ra0, ra1, rb0, rb1;
        dot16x2(x2p0, x2p1, &sh_color2[j * C], ra0, ra1);
        dot16x2(x2p0, x2p1, &sh_color2[(j + 1) * C], rb0, rb1);
        a2p0[j >> 1] = pack2(fmaf(ra0, sh_a2[j], sh_b2[j]), fmaf(rb0, sh_a2[j + 1], sh_b2[j + 1]));
        a2p1[j >> 1] = pack2(fmaf(ra1, sh_a2[j], sh_b2[j]), fmaf(rb1, sh_a2[j + 1], sh_b2[j + 1]));
    }

    // ---- MLP fc1 -> GELU -> fc2 (h1 never stored) ----
    u64 fo0[8] = {0, 0, 0, 0, 0, 0, 0, 0}, fo1[8] = {0, 0, 0, 0, 0, 0, 0, 0};
#pragma unroll 8
    for (int j = 0; j < HID; j++) {
        float t0, t1;
        dot16x2(a2p0, a2p1, &sh_fc1w[j * C], t0, t1);
        t0 += sh_fc1b[j]; t1 += sh_fc1b[j];
        float u0 = 0.7978845608028654f * fmaf(0.044715f * t0, t0 * t0, t0);
        float u1 = 0.7978845608028654f * fmaf(0.044715f * t1, t1 * t1, t1);
        float g0 = 0.5f * t0 * (1.f + ftanh(u0));
        float g1 = 0.5f * t1 * (1.f + ftanh(u1));
        const ulonglong2* wp = (const ulonglong2*)&sh_fc2wt[j * C];
        ulonglong2 w0 = wp[0], w1 = wp[1], w2 = wp[2], w3 = wp[3];
        u64 gg0 = pack2(g0, g0), gg1 = pack2(g1, g1);
        ffma2(fo0[0], gg0, w0.x); ffma2(fo0[1], gg0, w0.y);
        ffma2(fo0[2], gg0, w1.x); ffma2(fo0[3], gg0, w1.y);
        ffma2(fo0[4], gg0, w2.x); ffma2(fo0[5], gg0, w2.y);
        ffma2(fo0[6], gg0, w3.x); ffma2(fo0[7], gg0, w3.y);
        ffma2(fo1[0], gg1, w0.x); ffma2(fo1[1], gg1, w0.y);
        ffma2(fo1[2], gg1, w1.x); ffma2(fo1[3], gg1, w1.y);
        ffma2(fo1[4], gg1, w2.x); ffma2(fo1[5], gg1, w2.y);
        ffma2(fo1[6], gg1, w3.x); ffma2(fo1[7], gg1, w3.y);
    }

    // ---- residual + NCHW write (2 tokens) ----
    float* ob = out + (size_t)b * C * HH * WW;
    const int gx = x0 + w * 8 + tx;
    const int gy0 = y0 + ty0, gy1 = y0 + ty0 + 4;
#pragma unroll
    for (int i = 0; i < 8; i++) {
        float lo0, hi0, lo1, hi1, xa0, xb0, xa1, xb1;
        unpack2(fo0[i], lo0, hi0); unpack2(fo1[i], lo1, hi1);
        unpack2(x2p0[i], xa0, xb0); unpack2(x2p1[i], xa1, xb1);
        int c0 = 2 * i;
        ob[c0 * (HH * WW) + gy0 * WW + gx]       = xa0 + sh_fc2b[c0]     + lo0;
        ob[(c0 + 1) * (HH * WW) + gy0 * WW + gx] = xb0 + sh_fc2b[c0 + 1] + hi0;
        ob[c0 * (HH * WW) + gy1 * WW + gx]       = xa1 + sh_fc2b[c0]     + lo1;
        ob[(c0 + 1) * (HH * WW) + gy1 * WW + gx] = xb1 + sh_fc2b[c0 + 1] + hi1;
    }
#undef HALO
}

extern "C" void kernel_launch(void* const* d_in, const int* in_sizes, int n_in,
                              void* d_out, int out_size) {
    (void)n_in; (void)out_size;
    const float* x      = (const float*)d_in[0];
    const float* pos_w  = (const float*)d_in[1];
    const float* pos_b  = (const float*)d_in[2];
    const float* alpha1 = (const float*)d_in[3];
    const float* beta1  = (const float*)d_in[4];
    const float* color1 = (const float*)d_in[5];
    const float* qkv_w  = (const float*)d_in[6];
    const float* qkv_b  = (const float*)d_in[7];
    const float* proj_w = (const float*)d_in[8];
    const float* proj_b = (const float*)d_in[9];
    const float* alpha2 = (const float*)d_in[10];
    const float* beta2  = (const float*)d_in[11];
    const float* color2 = (const float*)d_in[12];
    const float* fc1_w  = (const float*)d_in[13];
    const float* fc1_b  = (const float*)d_in[14];
    const float* fc2_w  = (const float*)d_in[15];
    const float* fc2_b  = (const float*)d_in[16];

    int B = in_sizes[0] / (C * HH * WW);
    dim3 grid(WW / (2 * WS), HH / WS, B);
    swin_fused_kernel<<<grid, 64>>>(
        x, pos_w, pos_b, alpha1, beta1, color1, qkv_w, qkv_b,
        proj_w, proj_b, alpha2, beta2, color2, fc1_w, fc1_b, fc2_w, fc2_b,
        (float*)d_out);
}

// round 6
// speedup vs baseline: 1.3674x; 1.0423x over previous
#include <cuda_runtime.h>

#define C 16
#define HEADS 2
#define HD 8
#define WS 8
#define HID 64
#define HH 512
#define WW 512
#define NTOK 64

typedef unsigned long long u64;

__device__ __forceinline__ u64 pack2(float a, float b) {
    u64 r; asm("mov.b64 %0, {%1,%2};" : "=l"(r) : "f"(a), "f"(b)); return r;
}
__device__ __forceinline__ void unpack2(u64 v, float& a, float& b) {
    asm("mov.b64 {%0,%1}, %2;" : "=f"(a), "=f"(b) : "l"(v));
}
__device__ __forceinline__ void ffma2(u64& d, u64 a, u64 b) {
    asm("fma.rn.f32x2 %0, %1, %2, %0;" : "+l"(d) : "l"(a), "l"(b));
}
__device__ __forceinline__ float fexp(float x) {
    float r; asm("ex2.approx.f32 %0, %1;" : "=f"(r) : "f"(x * 1.4426950408889634f)); return r;
}
__device__ __forceinline__ float ftanh(float x) {
    float r; asm("tanh.approx.f32 %0, %1;" : "=f"(r) : "f"(x)); return r;
}
__device__ __forceinline__ float hsum2(u64 a, u64 b) {
    float x0, x1, y0, y1; unpack2(a, x0, x1); unpack2(b, y0, y1);
    return (x0 + x1) + (y0 + y1);
}

// 16-wide dot for TWO tokens sharing one weight row (4x LDS.128, 16 ffma2)
__device__ __forceinline__ void dot16x2(const u64* a0, const u64* a1,
                                        const float* w, float& r0, float& r1) {
    const ulonglong2* wp = reinterpret_cast<const ulonglong2*>(w);
    ulonglong2 w0 = wp[0], w1 = wp[1], w2 = wp[2], w3 = wp[3];
    u64 p0 = 0, q0 = 0, p1 = 0, q1 = 0;
    ffma2(p0, a0[0], w0.x); ffma2(q0, a0[1], w0.y);
    ffma2(p0, a0[2], w1.x); ffma2(q0, a0[3], w1.y);
    ffma2(p0, a0[4], w2.x); ffma2(q0, a0[5], w2.y);
    ffma2(p0, a0[6], w3.x); ffma2(q0, a0[7], w3.y);
    ffma2(p1, a1[0], w0.x); ffma2(q1, a1[1], w0.y);
    ffma2(p1, a1[2], w1.x); ffma2(q1, a1[3], w1.y);
    ffma2(p1, a1[4], w2.x); ffma2(q1, a1[5], w2.y);
    ffma2(p1, a1[6], w3.x); ffma2(q1, a1[7], w3.y);
    r0 = hsum2(p0, q0); r1 = hsum2(p1, q1);
}

__global__ __launch_bounds__(64, 7) void swin_fused_kernel(
    const float* __restrict__ x,
    const float* __restrict__ pos_w, const float* __restrict__ pos_b,
    const float* __restrict__ alpha1, const float* __restrict__ beta1, const float* __restrict__ color1,
    const float* __restrict__ qkv_w, const float* __restrict__ qkv_b,
    const float* __restrict__ proj_w, const float* __restrict__ proj_b,
    const float* __restrict__ alpha2, const float* __restrict__ beta2, const float* __restrict__ color2,
    const float* __restrict__ fc1_w, const float* __restrict__ fc1_b,
    const float* __restrict__ fc2_w, const float* __restrict__ fc2_b,
    float* __restrict__ out)
{
    // union buffer: halo [16][10][18] (2880 floats) THEN k/v [2 win][2 h][64][8]
    __shared__ __align__(16) float sh_dyn[4096];
    __shared__ __align__(16) float sh_color1[C * C];
    __shared__ __align__(16) float sh_qkvw[48 * C];
    __shared__ __align__(16) float sh_projw[C * C];
    __shared__ __align__(16) float sh_color2[C * C];
    __shared__ __align__(16) float sh_fc1w[HID * C];
    __shared__ __align__(16) float sh_fc2wt[HID * C];   // transposed [j][c2]
    __shared__ __align__(16) float sh_posw[C * 9];
    __shared__ float sh_posb[C], sh_a1[C], sh_b1[C], sh_qkvb[48];
    __shared__ float sh_projb[C], sh_a2[C], sh_b2[C], sh_fc1b[HID], sh_fc2b[C];

    const int tid = threadIdx.x;
    const int b  = blockIdx.z;
    const int y0 = blockIdx.y * WS;
    const int x0 = blockIdx.x * (2 * WS);    // CTA covers 2 horizontal windows

    // ---- cooperative weight loads ----
    for (int i = tid; i < C * C; i += 64) {
        sh_color1[i] = color1[i];
        sh_projw[i]  = proj_w[i];
        sh_color2[i] = color2[i];
    }
    for (int i = tid; i < 48 * C; i += 64) sh_qkvw[i] = qkv_w[i];
    for (int i = tid; i < HID * C; i += 64) {
        sh_fc1w[i] = fc1_w[i];
        int c2 = i >> 6, j = i & 63;
        sh_fc2wt[j * C + c2] = fc2_w[i];
    }
    for (int i = tid; i < C * 9; i += 64) sh_posw[i] = pos_w[i];
    if (tid < C) {
        sh_posb[tid] = pos_b[tid];
        sh_a1[tid] = alpha1[tid]; sh_b1[tid] = beta1[tid];
        sh_projb[tid] = proj_b[tid];
        sh_a2[tid] = alpha2[tid]; sh_b2[tid] = beta2[tid];
        sh_fc2b[tid] = fc2_b[tid];
    }
    if (tid < 48) sh_qkvb[tid] = qkv_b[tid];
    sh_fc1b[tid] = fc1_b[tid];

    // ---- halo load: [C][10][18] with zero padding ----
    const float* xb = x + (size_t)b * C * HH * WW;
#define HALO(c, r, cc) sh_dyn[(c) * 180 + (r) * 18 + (cc)]
    for (int i = tid; i < C * 180; i += 64) {
        int c = i / 180, rem = i - c * 180;
        int r = rem / 18, cc = rem - r * 18;
        int gy = y0 - 1 + r, gx = x0 - 1 + cc;
        float v = 0.f;
        if ((unsigned)gy < HH && (unsigned)gx < WW)
            v = xb[c * (HH * WW) + gy * WW + gx];
        sh_dyn[i] = v;
    }
    __syncthreads();

    // thread t: window w = t>>5; owns tokens (ty0,tx) and (ty0+4,tx) of window w
    const int w = tid >> 5, lane = tid & 31;
    const int ty0 = lane >> 3, tx = lane & 7;
    const int hc = w * 8 + tx;   // halo col base

    // ---- depthwise 3x3 conv + residual + bias (exact fp32 shortcut) ----
    float s0[C], s1[C];
#pragma unroll
    for (int c = 0; c < C; c++) {
        float a0 = HALO(c, ty0 + 1, hc + 1) + sh_posb[c];
        float a1 = HALO(c, ty0 + 5, hc + 1) + sh_posb[c];
#pragma unroll
        for (int di = 0; di < 3; di++)
#pragma unroll
            for (int dj = 0; dj < 3; dj++) {
                float wgt = sh_posw[c * 9 + di * 3 + dj];
                a0 = fmaf(HALO(c, ty0 + di,     hc + dj), wgt, a0);
                a1 = fmaf(HALO(c, ty0 + 4 + di, hc + dj), wgt, a1);
            }
        s0[c] = a0; s1[c] = a1;
    }
    __syncthreads();   // halo reads done -> sh_dyn reusable as K/V

    float* sh_k = sh_dyn;          // [((w*2+h)*64 + m)*8 + d]
    float* sh_v = sh_dyn + 2048;

    u64 sp0[8], sp1[8];
#pragma unroll
    for (int i = 0; i < 8; i++) {
        sp0[i] = pack2(s0[2 * i], s0[2 * i + 1]);
        sp1[i] = pack2(s1[2 * i], s1[2 * i + 1]);
    }

    // ---- aff1 ----
    u64 yp0[8], yp1[8];
#pragma unroll
    for (int j = 0; j < C; j += 2) {
        float ra0, ra1, rb0, rb1;
        dot16x2(sp0, sp1, &sh_color1[j * C], ra0, ra1);
        dot16x2(sp0, sp1, &sh_color1[(j + 1) * C], rb0, rb1);
        yp0[j >> 1] = pack2(fmaf(ra0, sh_a1[j], sh_b1[j]), fmaf(rb0, sh_a1[j + 1], sh_b1[j + 1]));
        yp1[j >> 1] = pack2(fmaf(ra1, sh_a1[j], sh_b1[j]), fmaf(rb1, sh_a1[j + 1], sh_b1[j + 1]));
    }

    // ---- qkv: Q to regs, K/V streamed straight to smem (no register spike) ----
    const float SCL = 0.35355339059327373f;   // hd^-0.5
    u64 qp0[2][4], qp1[2][4];
#pragma unroll
    for (int j = 0; j < C; j += 2) {
        float ra0, ra1, rb0, rb1;
        dot16x2(yp0, yp1, &sh_qkvw[j * C], ra0, ra1);
        dot16x2(yp0, yp1, &sh_qkvw[(j + 1) * C], rb0, rb1);
        ra0 = (ra0 + sh_qkvb[j]) * SCL;     rb0 = (rb0 + sh_qkvb[j + 1]) * SCL;
        ra1 = (ra1 + sh_qkvb[j]) * SCL;     rb1 = (rb1 + sh_qkvb[j + 1]) * SCL;
        qp0[j >> 3][(j & 7) >> 1] = pack2(ra0, rb0);
        qp1[j >> 3][(j & 7) >> 1] = pack2(ra1, rb1);
    }
#pragma unroll
    for (int j = 0; j < C; j += 2) {          // K: channel pair -> STS.64 x2
        float ra0, ra1, rb0, rb1;
        dot16x2(yp0, yp1, &sh_qkvw[(16 + j) * C], ra0, ra1);
        dot16x2(yp0, yp1, &sh_qkvw[(16 + j + 1) * C], rb0, rb1);
        int h = j >> 3, d = j & 7;
        float* base = &sh_k[((w * 2 + h) * 64 + lane) * 8 + d];
        *(float2*)base           = make_float2(ra0 + sh_qkvb[16 + j], rb0 + sh_qkvb[16 + j + 1]);
        *(float2*)(base + 256)   = make_float2(ra1 + sh_qkvb[16 + j], rb1 + sh_qkvb[16 + j + 1]);
    }
#pragma unroll
    for (int j = 0; j < C; j += 2) {          // V
        float ra0, ra1, rb0, rb1;
        dot16x2(yp0, yp1, &sh_qkvw[(32 + j) * C], ra0, ra1);
        dot16x2(yp0, yp1, &sh_qkvw[(32 + j + 1) * C], rb0, rb1);
        int h = j >> 3, d = j & 7;
        float* base = &sh_v[((w * 2 + h) * 64 + lane) * 8 + d];
        *(float2*)base           = make_float2(ra0 + sh_qkvb[32 + j], rb0 + sh_qkvb[32 + j + 1]);
        *(float2*)(base + 256)   = make_float2(ra1 + sh_qkvb[32 + j], rb1 + sh_qkvb[32 + j + 1]);
    }
    __syncwarp();   // K/V are warp-private (warp == window)

    // ---- window attention, no-max online softmax (logits ~ +-0.1) ----
    u64 aop0[8], aop1[8];
#pragma unroll
    for (int h = 0; h < HEADS; h++) {
        const ulonglong2* kb = (const ulonglong2*)&sh_k[(w * 2 + h) * 64 * 8];
        const ulonglong2* vb = (const ulonglong2*)&sh_v[(w * 2 + h) * 64 * 8];
        float sA0 = 0.f, sB0 = 0.f, sA1 = 0.f, sB1 = 0.f;   // split sum chains
        u64 o0[4] = {0, 0, 0, 0}, o1[4] = {0, 0, 0, 0};
#pragma unroll 4
        for (int m = 0; m < NTOK; m++) {
            ulonglong2 ka = kb[2 * m], kc = kb[2 * m + 1];
            u64 d0a = 0, d0b = 0, d1a = 0, d1b = 0;
            ffma2(d0a, qp0[h][0], ka.x); ffma2(d0b, qp0[h][1], ka.y);
            ffma2(d0a, qp0[h][2], kc.x); ffma2(d0b, qp0[h][3], kc.y);
            ffma2(d1a, qp1[h][0], ka.x); ffma2(d1b, qp1[h][1], ka.y);
            ffma2(d1a, qp1[h][2], kc.x); ffma2(d1b, qp1[h][3], kc.y);
            float p0 = fexp(hsum2(d0a, d0b));
            float p1 = fexp(hsum2(d1a, d1b));
            if (m & 1) { sB0 += p0; sB1 += p1; }
            else       { sA0 += p0; sA1 += p1; }
            ulonglong2 va = vb[2 * m], vc = vb[2 * m + 1];
            u64 pp0 = pack2(p0, p0), pp1 = pack2(p1, p1);
            ffma2(o0[0], pp0, va.x); ffma2(o0[1], pp0, va.y);
            ffma2(o0[2], pp0, vc.x); ffma2(o0[3], pp0, vc.y);
            ffma2(o1[0], pp1, va.x); ffma2(o1[1], pp1, va.y);
            ffma2(o1[2], pp1, vc.x); ffma2(o1[3], pp1, vc.y);
        }
        float r0 = 1.0f / (sA0 + sB0), r1 = 1.0f / (sA1 + sB1);
        u64 rr0 = pack2(r0, r0), rr1 = pack2(r1, r1);
#pragma unroll
        for (int i = 0; i < 4; i++) {
            u64 t0 = 0, t1 = 0;
            ffma2(t0, o0[i], rr0);
            ffma2(t1, o1[i], rr1);
            aop0[h * 4 + i] = t0;
            aop1[h * 4 + i] = t1;
        }
    }

    // ---- proj + residual ----
    u64 x2p0[8], x2p1[8];
#pragma unroll
    for (int j = 0; j < C; j += 2) {
        float ra0, ra1, rb0, rb1;
        dot16x2(aop0, aop1, &sh_projw[j * C], ra0, ra1);
        dot16x2(aop0, aop1, &sh_projw[(j + 1) * C], rb0, rb1);
        float sa0, sa1, sb0, sb1;
        unpack2(sp0[j >> 1], sa0, sb0);
        unpack2(sp1[j >> 1], sa1, sb1);
        x2p0[j >> 1] = pack2(sa0 + ra0 + sh_projb[j], sb0 + rb0 + sh_projb[j + 1]);
        x2p1[j >> 1] = pack2(sa1 + ra1 + sh_projb[j], sb1 + rb1 + sh_projb[j + 1]);
    }

    // ---- aff2 ----
    u64 a2p0[8], a2p1[8];
#pragma unroll
    for (int j = 0; j < C; j += 2) {
        float ra0, ra1, rb0, rb1;
        dot16x2(x2p0, x2p1, &sh_color2[j * C], ra0, ra1);
        dot16x2(x2p0, x2p1, &sh_color2[(j + 1) * C], rb0, rb1);
        a2p0[j >> 1] = pack2(fmaf(ra0, sh_a2[j], sh_b2[j]), fmaf(rb0, sh_a2[j + 1], sh_b2[j + 1]));
        a2p1[j >> 1] = pack2(fmaf(ra1, sh_a2[j], sh_b2[j]), fmaf(rb1, sh_a2[j + 1], sh_b2[j + 1]));
    }

    // ---- MLP fc1 -> GELU -> fc2 (h1 never stored) ----
    u64 fo0[8] = {0, 0, 0, 0, 0, 0, 0, 0}, fo1[8] = {0, 0, 0, 0, 0, 0, 0, 0};
#pragma unroll 8
    for (int j = 0; j < HID; j++) {
        float t0, t1;
        dot16x2(a2p0, a2p1, &sh_fc1w[j * C], t0, t1);
        t0 += sh_fc1b[j]; t1 += sh_fc1b[j];
        float u0 = 0.7978845608028654f * fmaf(0.044715f * t0, t0 * t0, t0);
        float u1 = 0.7978845608028654f * fmaf(0.044715f * t1, t1 * t1, t1);
        float g0 = 0.5f * t0 * (1.f + ftanh(u0));
        float g1 = 0.5f * t1 * (1.f + ftanh(u1));
        const ulonglong2* wp = (const ulonglong2*)&sh_fc2wt[j * C];
        ulonglong2 w0 = wp[0], w1 = wp[1], w2 = wp[2], w3 = wp[3];
        u64 gg0 = pack2(g0, g0), gg1 = pack2(g1, g1);
        ffma2(fo0[0], gg0, w0.x); ffma2(fo0[1], gg0, w0.y);
        ffma2(fo0[2], gg0, w1.x); ffma2(fo0[3], gg0, w1.y);
        ffma2(fo0[4], gg0, w2.x); ffma2(fo0[5], gg0, w2.y);
        ffma2(fo0[6], gg0, w3.x); ffma2(fo0[7], gg0, w3.y);
        ffma2(fo1[0], gg1, w0.x); ffma2(fo1[1], gg1, w0.y);
        ffma2(fo1[2], gg1, w1.x); ffma2(fo1[3], gg1, w1.y);
        ffma2(fo1[4], gg1, w2.x); ffma2(fo1[5], gg1, w2.y);
        ffma2(fo1[6], gg1, w3.x); ffma2(fo1[7], gg1, w3.y);
    }

    // ---- residual + NCHW write (2 tokens) ----
    float* ob = out + (size_t)b * C * HH * WW;
    const int gx = x0 + w * 8 + tx;
    const int gy0 = y0 + ty0, gy1 = y0 + ty0 + 4;
#pragma unroll
    for (int i = 0; i < 8; i++) {
        float lo0, hi0, lo1, hi1, xa0, xb0, xa1, xb1;
        unpack2(fo0[i], lo0, hi0); unpack2(fo1[i], lo1, hi1);
        unpack2(x2p0[i], xa0, xb0); unpack2(x2p1[i], xa1, xb1);
        int c0 = 2 * i;
        ob[c0 * (HH * WW) + gy0 * WW + gx]       = xa0 + sh_fc2b[c0]     + lo0;
        ob[(c0 + 1) * (HH * WW) + gy0 * WW + gx] = xb0 + sh_fc2b[c0 + 1] + hi0;
        ob[c0 * (HH * WW) + gy1 * WW + gx]       = xa1 + sh_fc2b[c0]     + lo1;
        ob[(c0 + 1) * (HH * WW) + gy1 * WW + gx] = xb1 + sh_fc2b[c0 + 1] + hi1;
    }
#undef HALO
}

extern "C" void kernel_launch(void* const* d_in, const int* in_sizes, int n_in,
                              void* d_out, int out_size) {
    (void)n_in; (void)out_size;
    const float* x      = (const float*)d_in[0];
    const float* pos_w  = (const float*)d_in[1];
    const float* pos_b  = (const float*)d_in[2];
    const float* alpha1 = (const float*)d_in[3];
    const float* beta1  = (const float*)d_in[4];
    const float* color1 = (const float*)d_in[5];
    const float* qkv_w  = (const float*)d_in[6];
    const float* qkv_b  = (const float*)d_in[7];
    const float* proj_w = (const float*)d_in[8];
    const float* proj_b = (const float*)d_in[9];
    const float* alpha2 = (const float*)d_in[10];
    const float* beta2  = (const float*)d_in[11];
    const float* color2 = (const float*)d_in[12];
    const float* fc1_w  = (const float*)d_in[13];
    const float* fc1_b  = (const float*)d_in[14];
    const float* fc2_w  = (const float*)d_in[15];
    const float* fc2_b  = (const float*)d_in[16];

    int B = in_sizes[0] / (C * HH * WW);
    dim3 grid(WW / (2 * WS), HH / WS, B);
    swin_fused_kernel<<<grid, 64>>>(
        x, pos_w, pos_b, alpha1, beta1, color1, qkv_w, qkv_b,
        proj_w, proj_b, alpha2, beta2, color2, fc1_w, fc1_b, fc2_w, fc2_b,
        (float*)d_out);
}

// round 7
// speedup vs baseline: 1.5233x; 1.1140x over previous
#include <cuda_runtime.h>

#define C 16
#define HEADS 2
#define HD 8
#define WS 8
#define HID 64
#define HH 512
#define WW 512
#define NTOK 64
#define CTAW 4          // windows per CTA
#define NTHR 128

typedef unsigned long long u64;

// -------- folded weights (prep kernel -> main kernel) --------
__device__ float g_qkvw[48 * C];   // aff1-folded qkv weight; Q rows pre-scaled by hd^-0.5*log2e
__device__ float g_qkvb[48];
__device__ float g_fc1w[HID * C];  // aff2-folded fc1 weight
__device__ float g_fc1b[HID];
__device__ float g_fc2wt[HID * C]; // fc2_w transposed: [j][c]

__device__ __forceinline__ u64 pack2(float a, float b) {
    u64 r; asm("mov.b64 %0, {%1,%2};" : "=l"(r) : "f"(a), "f"(b)); return r;
}
__device__ __forceinline__ void unpack2(u64 v, float& a, float& b) {
    asm("mov.b64 {%0,%1}, %2;" : "=f"(a), "=f"(b) : "l"(v));
}
__device__ __forceinline__ void ffma2(u64& d, u64 a, u64 b) {
    asm("fma.rn.f32x2 %0, %1, %2, %0;" : "+l"(d) : "l"(a), "l"(b));
}
__device__ __forceinline__ float fexp2(float x) {   // 2^x
    float r; asm("ex2.approx.f32 %0, %1;" : "=f"(r) : "f"(x)); return r;
}
__device__ __forceinline__ float ftanh(float x) {
    float r; asm("tanh.approx.f32 %0, %1;" : "=f"(r) : "f"(x)); return r;
}
__device__ __forceinline__ float hsum2(u64 a, u64 b) {
    float x0, x1, y0, y1; unpack2(a, x0, x1); unpack2(b, y0, y1);
    return (x0 + x1) + (y0 + y1);
}

// 16-wide dot for TWO tokens sharing one weight row (4x LDS.128, 16 ffma2)
__device__ __forceinline__ void dot16x2(const u64* a0, const u64* a1,
                                        const float* w, float& r0, float& r1) {
    const ulonglong2* wp = reinterpret_cast<const ulonglong2*>(w);
    ulonglong2 w0 = wp[0], w1 = wp[1], w2 = wp[2], w3 = wp[3];
    u64 p0 = 0, q0 = 0, p1 = 0, q1 = 0;
    ffma2(p0, a0[0], w0.x); ffma2(q0, a0[1], w0.y);
    ffma2(p0, a0[2], w1.x); ffma2(q0, a0[3], w1.y);
    ffma2(p0, a0[4], w2.x); ffma2(q0, a0[5], w2.y);
    ffma2(p0, a0[6], w3.x); ffma2(q0, a0[7], w3.y);
    ffma2(p1, a1[0], w0.x); ffma2(q1, a1[1], w0.y);
    ffma2(p1, a1[2], w1.x); ffma2(q1, a1[3], w1.y);
    ffma2(p1, a1[4], w2.x); ffma2(q1, a1[5], w2.y);
    ffma2(p1, a1[6], w3.x); ffma2(q1, a1[7], w3.y);
    r0 = hsum2(p0, q0); r1 = hsum2(p1, q1);
}

// ---------------- prep: fold aff layers into GEMM weights ----------------
__global__ void prep_kernel(
    const float* __restrict__ alpha1, const float* __restrict__ beta1, const float* __restrict__ color1,
    const float* __restrict__ qkv_w, const float* __restrict__ qkv_b,
    const float* __restrict__ alpha2, const float* __restrict__ beta2, const float* __restrict__ color2,
    const float* __restrict__ fc1_w, const float* __restrict__ fc1_b,
    const float* __restrict__ fc2_w)
{
    const int t = threadIdx.x;   // 256 threads
    const float QSCL = 0.35355339059327373f * 1.4426950408889634f; // hd^-0.5 * log2(e)
    // qkv': W'[j][c] = sum_k qkv_w[j][k] * alpha1[k] * color1[k][c]
    for (int e = t; e < 48 * C; e += 256) {
        int j = e >> 4, c = e & 15;
        float acc = 0.f;
        for (int k = 0; k < C; k++)
            acc += qkv_w[j * C + k] * alpha1[k] * color1[k * C + c];
        g_qkvw[e] = (j < 16) ? acc * QSCL : acc;
    }
    if (t < 48) {
        float bb = qkv_b[t];
        for (int k = 0; k < C; k++) bb += qkv_w[t * C + k] * beta1[k];
        g_qkvb[t] = (t < 16) ? bb * QSCL : bb;
    }
    // fc1': W'[j][c] = sum_k fc1_w[j][k] * alpha2[k] * color2[k][c]
    for (int e = t; e < HID * C; e += 256) {
        int j = e >> 4, c = e & 15;
        float acc = 0.f;
        for (int k = 0; k < C; k++)
            acc += fc1_w[j * C + k] * alpha2[k] * color2[k * C + c];
        g_fc1w[e] = acc;
    }
    if (t < HID) {
        float bb = fc1_b[t];
        for (int k = 0; k < C; k++) bb += fc1_w[t * C + k] * beta2[k];
        g_fc1b[t] = bb;
    }
    // fc2 transpose: fc2_w[C][HID] -> g_fc2wt[j][c]
    for (int e = t; e < HID * C; e += 256) {
        int j = e >> 4, c = e & 15;
        g_fc2wt[e] = fc2_w[c * HID + j];
    }
}

// ---------------- main fused kernel: 128 threads = 4 windows ----------------
__global__ __launch_bounds__(NTHR, 4) void swin_fused_kernel(
    const float* __restrict__ x,
    const float* __restrict__ pos_w, const float* __restrict__ pos_b,
    const float* __restrict__ proj_w, const float* __restrict__ proj_b,
    const float* __restrict__ fc2_b,
    float* __restrict__ out)
{
    // union: halo [16][10][34] (5440 f)  THEN  K[4w][2h][64][8] + V same (8192 f)
    __shared__ __align__(16) float sh_dyn[8192];
    __shared__ __align__(16) float sh_qkvw[48 * C];
    __shared__ __align__(16) float sh_projw[C * C];
    __shared__ __align__(16) float sh_fc1w[HID * C];
    __shared__ __align__(16) float sh_fc2wt[HID * C];
    __shared__ __align__(16) float sh_posw[C * 9];
    __shared__ float sh_qkvb[48], sh_projb[C], sh_fc1b[HID], sh_fc2b[C], sh_posb[C];

    const int tid = threadIdx.x;
    const int b  = blockIdx.z;
    const int y0 = blockIdx.y * WS;
    const int x0 = blockIdx.x * (CTAW * WS);   // 32 columns per CTA

    // ---- cooperative weight loads ----
    for (int i = tid; i < HID * C; i += NTHR) {
        sh_fc1w[i]  = g_fc1w[i];
        sh_fc2wt[i] = g_fc2wt[i];
    }
    for (int i = tid; i < 48 * C; i += NTHR) sh_qkvw[i] = g_qkvw[i];
    for (int i = tid; i < C * C; i += NTHR)  sh_projw[i] = proj_w[i];
    for (int i = tid; i < C * 9; i += NTHR)  sh_posw[i] = pos_w[i];
    if (tid < 48) sh_qkvb[tid] = g_qkvb[tid];
    if (tid < HID) sh_fc1b[tid] = g_fc1b[tid];
    if (tid < C) {
        sh_projb[tid] = proj_b[tid];
        sh_fc2b[tid]  = fc2_b[tid];
        sh_posb[tid]  = pos_b[tid];
    }

    // ---- halo load: [C][10][34] with zero padding ----
    const float* xb = x + (size_t)b * C * HH * WW;
#define HALO(c, r, cc) sh_dyn[(c) * 340 + (r) * 34 + (cc)]
    for (int i = tid; i < C * 340; i += NTHR) {
        int c = i / 340, rem = i - c * 340;
        int r = rem / 34, cc = rem - r * 34;
        int gy = y0 - 1 + r, gx = x0 - 1 + cc;
        float v = 0.f;
        if ((unsigned)gy < HH && (unsigned)gx < WW)
            v = xb[c * (HH * WW) + gy * WW + gx];
        sh_dyn[i] = v;
    }
    __syncthreads();

    // warp w handles window w; thread owns tokens (ty0,tx) and (ty0+4,tx)
    const int w = tid >> 5, lane = tid & 31;
    const int ty0 = lane >> 3, tx = lane & 7;
    const int hc = w * 8 + tx;

    // ---- depthwise 3x3 conv + residual + bias -> exact fp32 shortcut ----
    float s0[C], s1[C];
#pragma unroll
    for (int c = 0; c < C; c++) {
        float a0 = HALO(c, ty0 + 1, hc + 1) + sh_posb[c];
        float a1 = HALO(c, ty0 + 5, hc + 1) + sh_posb[c];
#pragma unroll
        for (int di = 0; di < 3; di++)
#pragma unroll
            for (int dj = 0; dj < 3; dj++) {
                float wgt = sh_posw[c * 9 + di * 3 + dj];
                a0 = fmaf(HALO(c, ty0 + di,     hc + dj), wgt, a0);
                a1 = fmaf(HALO(c, ty0 + 4 + di, hc + dj), wgt, a1);
            }
        s0[c] = a0; s1[c] = a1;
    }
    __syncthreads();   // all halo reads done -> sh_dyn becomes K/V

    float* sh_k = sh_dyn;              // [((w*2+h)*64 + m)*8 + d]
    float* sh_v = sh_dyn + 4096;

    u64 sp0[8], sp1[8];
#pragma unroll
    for (int i = 0; i < 8; i++) {
        sp0[i] = pack2(s0[2 * i], s0[2 * i + 1]);
        sp1[i] = pack2(s1[2 * i], s1[2 * i + 1]);
    }

    // ---- qkv directly from shortcut (aff1 folded); Q rows pre-scaled ----
    u64 qp0[2][4], qp1[2][4];
#pragma unroll
    for (int j = 0; j < C; j += 2) {
        float ra0, ra1, rb0, rb1;
        dot16x2(sp0, sp1, &sh_qkvw[j * C], ra0, ra1);
        dot16x2(sp0, sp1, &sh_qkvw[(j + 1) * C], rb0, rb1);
        qp0[j >> 3][(j & 7) >> 1] = pack2(ra0 + sh_qkvb[j], rb0 + sh_qkvb[j + 1]);
        qp1[j >> 3][(j & 7) >> 1] = pack2(ra1 + sh_qkvb[j], rb1 + sh_qkvb[j + 1]);
    }
#pragma unroll
    for (int j = 0; j < C; j += 2) {          // K
        float ra0, ra1, rb0, rb1;
        dot16x2(sp0, sp1, &sh_qkvw[(16 + j) * C], ra0, ra1);
        dot16x2(sp0, sp1, &sh_qkvw[(16 + j + 1) * C], rb0, rb1);
        int h = j >> 3, d = j & 7;
        float* base = &sh_k[((w * 2 + h) * 64 + lane) * 8 + d];
        *(float2*)base         = make_float2(ra0 + sh_qkvb[16 + j], rb0 + sh_qkvb[16 + j + 1]);
        *(float2*)(base + 256) = make_float2(ra1 + sh_qkvb[16 + j], rb1 + sh_qkvb[16 + j + 1]);
    }
#pragma unroll
    for (int j = 0; j < C; j += 2) {          // V
        float ra0, ra1, rb0, rb1;
        dot16x2(sp0, sp1, &sh_qkvw[(32 + j) * C], ra0, ra1);
        dot16x2(sp0, sp1, &sh_qkvw[(32 + j + 1) * C], rb0, rb1);
        int h = j >> 3, d = j & 7;
        float* base = &sh_v[((w * 2 + h) * 64 + lane) * 8 + d];
        *(float2*)base         = make_float2(ra0 + sh_qkvb[32 + j], rb0 + sh_qkvb[32 + j + 1]);
        *(float2*)(base + 256) = make_float2(ra1 + sh_qkvb[32 + j], rb1 + sh_qkvb[32 + j + 1]);
    }
    __syncwarp();   // K/V are warp-private (warp == window)

    // ---- window attention; logits already in log2 domain -> bare ex2 ----
    u64 aop0[8], aop1[8];
#pragma unroll
    for (int h = 0; h < HEADS; h++) {
        const ulonglong2* kb = (const ulonglong2*)&sh_k[(w * 2 + h) * 64 * 8];
        const ulonglong2* vb = (const ulonglong2*)&sh_v[(w * 2 + h) * 64 * 8];
        float sA0 = 0.f, sB0 = 0.f, sA1 = 0.f, sB1 = 0.f;
        u64 o0[4] = {0, 0, 0, 0}, o1[4] = {0, 0, 0, 0};
#pragma unroll 4
        for (int m = 0; m < NTOK; m++) {
            ulonglong2 ka = kb[2 * m], kc = kb[2 * m + 1];
            u64 d0a = 0, d0b = 0, d1a = 0, d1b = 0;
            ffma2(d0a, qp0[h][0], ka.x); ffma2(d0b, qp0[h][1], ka.y);
            ffma2(d0a, qp0[h][2], kc.x); ffma2(d0b, qp0[h][3], kc.y);
            ffma2(d1a, qp1[h][0], ka.x); ffma2(d1b, qp1[h][1], ka.y);
            ffma2(d1a, qp1[h][2], kc.x); ffma2(d1b, qp1[h][3], kc.y);
            float p0 = fexp2(hsum2(d0a, d0b));
            float p1 = fexp2(hsum2(d1a, d1b));
            if (m & 1) { sB0 += p0; sB1 += p1; }
            else       { sA0 += p0; sA1 += p1; }
            ulonglong2 va = vb[2 * m], vc = vb[2 * m + 1];
            u64 pp0 = pack2(p0, p0), pp1 = pack2(p1, p1);
            ffma2(o0[0], pp0, va.x); ffma2(o0[1], pp0, va.y);
            ffma2(o0[2], pp0, vc.x); ffma2(o0[3], pp0, vc.y);
            ffma2(o1[0], pp1, va.x); ffma2(o1[1], pp1, va.y);
            ffma2(o1[2], pp1, vc.x); ffma2(o1[3], pp1, vc.y);
        }
        float r0 = 1.0f / (sA0 + sB0), r1 = 1.0f / (sA1 + sB1);
        u64 rr0 = pack2(r0, r0), rr1 = pack2(r1, r1);
#pragma unroll
        for (int i = 0; i < 4; i++) {
            u64 t0 = 0, t1 = 0;
            ffma2(t0, o0[i], rr0);
            ffma2(t1, o1[i], rr1);
            aop0[h * 4 + i] = t0;
            aop1[h * 4 + i] = t1;
        }
    }

    // ---- proj + residual -> x2 ----
    u64 x2p0[8], x2p1[8];
#pragma unroll
    for (int j = 0; j < C; j += 2) {
        float ra0, ra1, rb0, rb1;
        dot16x2(aop0, aop1, &sh_projw[j * C], ra0, ra1);
        dot16x2(aop0, aop1, &sh_projw[(j + 1) * C], rb0, rb1);
        float sa0, sa1, sb0, sb1;
        unpack2(sp0[j >> 1], sa0, sb0);
        unpack2(sp1[j >> 1], sa1, sb1);
        x2p0[j >> 1] = pack2(sa0 + ra0 + sh_projb[j], sb0 + rb0 + sh_projb[j + 1]);
        x2p1[j >> 1] = pack2(sa1 + ra1 + sh_projb[j], sb1 + rb1 + sh_projb[j + 1]);
    }

    // ---- MLP: fc1 (aff2 folded) -> GELU -> fc2 ----
    u64 fo0[8] = {0, 0, 0, 0, 0, 0, 0, 0}, fo1[8] = {0, 0, 0, 0, 0, 0, 0, 0};
#pragma unroll 8
    for (int j = 0; j < HID; j++) {
        float t0, t1;
        dot16x2(x2p0, x2p1, &sh_fc1w[j * C], t0, t1);
        t0 += sh_fc1b[j]; t1 += sh_fc1b[j];
        float u0 = 0.7978845608028654f * fmaf(0.044715f * t0, t0 * t0, t0);
        float u1 = 0.7978845608028654f * fmaf(0.044715f * t1, t1 * t1, t1);
        float g0 = 0.5f * t0 * (1.f + ftanh(u0));
        float g1 = 0.5f * t1 * (1.f + ftanh(u1));
        const ulonglong2* wp = (const ulonglong2*)&sh_fc2wt[j * C];
        ulonglong2 w0 = wp[0], w1 = wp[1], w2 = wp[2], w3 = wp[3];
        u64 gg0 = pack2(g0, g0), gg1 = pack2(g1, g1);
        ffma2(fo0[0], gg0, w0.x); ffma2(fo0[1], gg0, w0.y);
        ffma2(fo0[2], gg0, w1.x); ffma2(fo0[3], gg0, w1.y);
        ffma2(fo0[4], gg0, w2.x); ffma2(fo0[5], gg0, w2.y);
        ffma2(fo0[6], gg0, w3.x); ffma2(fo0[7], gg0, w3.y);
        ffma2(fo1[0], gg1, w0.x); ffma2(fo1[1], gg1, w0.y);
        ffma2(fo1[2], gg1, w1.x); ffma2(fo1[3], gg1, w1.y);
        ffma2(fo1[4], gg1, w2.x); ffma2(fo1[5], gg1, w2.y);
        ffma2(fo1[6], gg1, w3.x); ffma2(fo1[7], gg1, w3.y);
    }

    // ---- residual + NCHW write (2 tokens) ----
    float* ob = out + (size_t)b * C * HH * WW;
    const int gx = x0 + w * 8 + tx;
    const int gy0 = y0 + ty0, gy1 = y0 + ty0 + 4;
#pragma unroll
    for (int i = 0; i < 8; i++) {
        float lo0, hi0, lo1, hi1, xa0, xb0, xa1, xb1;
        unpack2(fo0[i], lo0, hi0); unpack2(fo1[i], lo1, hi1);
        unpack2(x2p0[i], xa0, xb0); unpack2(x2p1[i], xa1, xb1);
        int c0 = 2 * i;
        ob[c0 * (HH * WW) + gy0 * WW + gx]       = xa0 + sh_fc2b[c0]     + lo0;
        ob[(c0 + 1) * (HH * WW) + gy0 * WW + gx] = xb0 + sh_fc2b[c0 + 1] + hi0;
        ob[c0 * (HH * WW) + gy1 * WW + gx]       = xa1 + sh_fc2b[c0]     + lo1;
        ob[(c0 + 1) * (HH * WW) + gy1 * WW + gx] = xb1 + sh_fc2b[c0 + 1] + hi1;
    }
#undef HALO
}

extern "C" void kernel_launch(void* const* d_in, const int* in_sizes, int n_in,
                              void* d_out, int out_size) {
    (void)n_in; (void)out_size;
    const float* x      = (const float*)d_in[0];
    const float* pos_w  = (const float*)d_in[1];
    const float* pos_b  = (const float*)d_in[2];
    const float* alpha1 = (const float*)d_in[3];
    const float* beta1  = (const float*)d_in[4];
    const float* color1 = (const float*)d_in[5];
    const float* qkv_w  = (const float*)d_in[6];
    const float* qkv_b  = (const float*)d_in[7];
    const float* proj_w = (const float*)d_in[8];
    const float* proj_b = (const float*)d_in[9];
    const float* alpha2 = (const float*)d_in[10];
    const float* beta2  = (const float*)d_in[11];
    const float* color2 = (const float*)d_in[12];
    const float* fc1_w  = (const float*)d_in[13];
    const float* fc1_b  = (const float*)d_in[14];
    const float* fc2_w  = (const float*)d_in[15];
    const float* fc2_b  = (const float*)d_in[16];

    prep_kernel<<<1, 256>>>(alpha1, beta1, color1, qkv_w, qkv_b,
                            alpha2, beta2, color2, fc1_w, fc1_b, fc2_w);

    int B = in_sizes[0] / (C * HH * WW);
    dim3 grid(WW / (CTAW * WS), HH / WS, B);
    swin_fused_kernel<<<grid, NTHR>>>(
        x, pos_w, pos_b, proj_w, proj_b, fc2_b, (float*)d_out);
}

// round 8
// speedup vs baseline: 1.5362x; 1.0085x over previous
#include <cuda_runtime.h>

#define C 16
#define HEADS 2
#define HD 8
#define WS 8
#define HID 64
#define HH 512
#define WW 512
#define NTOK 64
#define CTAW 4          // windows per CTA
#define NTHR 128

typedef unsigned long long u64;

// -------- folded weights (prep kernel -> main kernel) --------
__device__ float g_qkvw[48 * C];   // aff1-folded qkv weight; Q rows pre-scaled by hd^-0.5*log2e
__device__ float g_qkvb[48];
__device__ float g_fc1w[HID * C];  // aff2-folded fc1 weight
__device__ float g_fc1b[HID];
__device__ float g_fc2wt[HID * C]; // fc2_w transposed: [j][c]

__device__ __forceinline__ u64 pack2(float a, float b) {
    u64 r; asm("mov.b64 %0, {%1,%2};" : "=l"(r) : "f"(a), "f"(b)); return r;
}
__device__ __forceinline__ void unpack2(u64 v, float& a, float& b) {
    asm("mov.b64 {%0,%1}, %2;" : "=f"(a), "=f"(b) : "l"(v));
}
__device__ __forceinline__ void ffma2(u64& d, u64 a, u64 b) {
    asm("fma.rn.f32x2 %0, %1, %2, %0;" : "+l"(d) : "l"(a), "l"(b));
}
__device__ __forceinline__ u64 fmul2(u64 a, u64 b) {
    u64 r; asm("mul.rn.f32x2 %0, %1, %2;" : "=l"(r) : "l"(a), "l"(b)); return r;
}
__device__ __forceinline__ float fexp2(float x) {   // 2^x
    float r; asm("ex2.approx.f32 %0, %1;" : "=f"(r) : "f"(x)); return r;
}
__device__ __forceinline__ float frcp(float x) {
    float r; asm("rcp.approx.f32 %0, %1;" : "=f"(r) : "f"(x)); return r;
}
__device__ __forceinline__ float ftanh(float x) {
    float r; asm("tanh.approx.f32 %0, %1;" : "=f"(r) : "f"(x)); return r;
}
__device__ __forceinline__ float hsum2(u64 a, u64 b) {
    float x0, x1, y0, y1; unpack2(a, x0, x1); unpack2(b, y0, y1);
    return (x0 + x1) + (y0 + y1);
}

// 16-wide dot for TWO tokens sharing one weight row (4x LDS.128, 16 ffma2)
__device__ __forceinline__ void dot16x2(const u64* a0, const u64* a1,
                                        const float* w, float& r0, float& r1) {
    const ulonglong2* wp = reinterpret_cast<const ulonglong2*>(w);
    ulonglong2 w0 = wp[0], w1 = wp[1], w2 = wp[2], w3 = wp[3];
    u64 p0 = 0, q0 = 0, p1 = 0, q1 = 0;
    ffma2(p0, a0[0], w0.x); ffma2(q0, a0[1], w0.y);
    ffma2(p0, a0[2], w1.x); ffma2(q0, a0[3], w1.y);
    ffma2(p0, a0[4], w2.x); ffma2(q0, a0[5], w2.y);
    ffma2(p0, a0[6], w3.x); ffma2(q0, a0[7], w3.y);
    ffma2(p1, a1[0], w0.x); ffma2(q1, a1[1], w0.y);
    ffma2(p1, a1[2], w1.x); ffma2(q1, a1[3], w1.y);
    ffma2(p1, a1[4], w2.x); ffma2(q1, a1[5], w2.y);
    ffma2(p1, a1[6], w3.x); ffma2(q1, a1[7], w3.y);
    r0 = hsum2(p0, q0); r1 = hsum2(p1, q1);
}

// ---------------- prep: fold aff layers into GEMM weights ----------------
__global__ void prep_kernel(
    const float* __restrict__ alpha1, const float* __restrict__ beta1, const float* __restrict__ color1,
    const float* __restrict__ qkv_w, const float* __restrict__ qkv_b,
    const float* __restrict__ alpha2, const float* __restrict__ beta2, const float* __restrict__ color2,
    const float* __restrict__ fc1_w, const float* __restrict__ fc1_b,
    const float* __restrict__ fc2_w)
{
    const int t = threadIdx.x;   // 256 threads
    const float QSCL = 0.35355339059327373f * 1.4426950408889634f; // hd^-0.5 * log2(e)
    for (int e = t; e < 48 * C; e += 256) {
        int j = e >> 4, c = e & 15;
        float acc = 0.f;
        for (int k = 0; k < C; k++)
            acc += qkv_w[j * C + k] * alpha1[k] * color1[k * C + c];
        g_qkvw[e] = (j < 16) ? acc * QSCL : acc;
    }
    if (t < 48) {
        float bb = qkv_b[t];
        for (int k = 0; k < C; k++) bb += qkv_w[t * C + k] * beta1[k];
        g_qkvb[t] = (t < 16) ? bb * QSCL : bb;
    }
    for (int e = t; e < HID * C; e += 256) {
        int j = e >> 4, c = e & 15;
        float acc = 0.f;
        for (int k = 0; k < C; k++)
            acc += fc1_w[j * C + k] * alpha2[k] * color2[k * C + c];
        g_fc1w[e] = acc;
    }
    if (t < HID) {
        float bb = fc1_b[t];
        for (int k = 0; k < C; k++) bb += fc1_w[t * C + k] * beta2[k];
        g_fc1b[t] = bb;
    }
    for (int e = t; e < HID * C; e += 256) {
        int j = e >> 4, c = e & 15;
        g_fc2wt[e] = fc2_w[c * HID + j];
    }
}

// ---------------- main fused kernel: 128 threads = 4 windows ----------------
__global__ __launch_bounds__(NTHR, 4) void swin_fused_kernel(
    const float* __restrict__ x,
    const float* __restrict__ pos_w, const float* __restrict__ pos_b,
    const float* __restrict__ proj_w, const float* __restrict__ proj_b,
    const float* __restrict__ fc2_b,
    float* __restrict__ out)
{
    // union: halo [16][10][34] (5440 f)  THEN  K[4w][2h][64][8] + V same (8192 f)
    __shared__ __align__(16) float sh_dyn[8192];
    __shared__ __align__(16) float sh_qkvw[48 * C];
    __shared__ __align__(16) float sh_projw[C * C];
    __shared__ __align__(16) float sh_fc1w[HID * C];
    __shared__ __align__(16) float sh_fc2wt[HID * C];
    __shared__ __align__(16) float sh_posw[C * 9];
    __shared__ float sh_qkvb[48], sh_projb[C], sh_fc1b[HID], sh_fc2b[C], sh_posb[C];

    const int tid = threadIdx.x;
    const int b  = blockIdx.z;
    const int y0 = blockIdx.y * WS;
    const int x0 = blockIdx.x * (CTAW * WS);   // 32 columns per CTA

    // ---- cooperative weight loads ----
    for (int i = tid; i < HID * C; i += NTHR) {
        sh_fc1w[i]  = g_fc1w[i];
        sh_fc2wt[i] = g_fc2wt[i];
    }
    for (int i = tid; i < 48 * C; i += NTHR) sh_qkvw[i] = g_qkvw[i];
    for (int i = tid; i < C * C; i += NTHR)  sh_projw[i] = proj_w[i];
    for (int i = tid; i < C * 9; i += NTHR)  sh_posw[i] = pos_w[i];
    if (tid < 48) sh_qkvb[tid] = g_qkvb[tid];
    if (tid < HID) sh_fc1b[tid] = g_fc1b[tid];
    if (tid < C) {
        sh_projb[tid] = proj_b[tid];
        sh_fc2b[tid]  = fc2_b[tid];
        sh_posb[tid]  = pos_b[tid];
    }

    // ---- halo load: [C][10][34] with zero padding ----
    const float* xb = x + (size_t)b * C * HH * WW;
#define HALO(c, r, cc) sh_dyn[(c) * 340 + (r) * 34 + (cc)]
    for (int i = tid; i < C * 340; i += NTHR) {
        int c = i / 340, rem = i - c * 340;
        int r = rem / 34, cc = rem - r * 34;
        int gy = y0 - 1 + r, gx = x0 - 1 + cc;
        float v = 0.f;
        if ((unsigned)gy < HH && (unsigned)gx < WW)
            v = xb[c * (HH * WW) + gy * WW + gx];
        sh_dyn[i] = v;
    }
    __syncthreads();

    // warp w handles window w; thread owns tokens (ty0,tx) and (ty0+4,tx)
    const int w = tid >> 5, lane = tid & 31;
    const int ty0 = lane >> 3, tx = lane & 7;
    const int hc = w * 8 + tx;

    // ---- depthwise 3x3 conv + residual + bias -> exact fp32 shortcut ----
    float s0[C], s1[C];
#pragma unroll
    for (int c = 0; c < C; c++) {
        float a0 = HALO(c, ty0 + 1, hc + 1) + sh_posb[c];
        float a1 = HALO(c, ty0 + 5, hc + 1) + sh_posb[c];
#pragma unroll
        for (int di = 0; di < 3; di++)
#pragma unroll
            for (int dj = 0; dj < 3; dj++) {
                float wgt = sh_posw[c * 9 + di * 3 + dj];
                a0 = fmaf(HALO(c, ty0 + di,     hc + dj), wgt, a0);
                a1 = fmaf(HALO(c, ty0 + 4 + di, hc + dj), wgt, a1);
            }
        s0[c] = a0; s1[c] = a1;
    }
    __syncthreads();   // all halo reads done -> sh_dyn becomes K/V

    float* sh_k = sh_dyn;              // [((w*2+h)*64 + m)*8 + d]
    float* sh_v = sh_dyn + 4096;

    u64 sp0[8], sp1[8];
#pragma unroll
    for (int i = 0; i < 8; i++) {
        sp0[i] = pack2(s0[2 * i], s0[2 * i + 1]);
        sp1[i] = pack2(s1[2 * i], s1[2 * i + 1]);
    }

    // ---- qkv directly from shortcut (aff1 folded); Q rows pre-scaled ----
    u64 qp0[2][4], qp1[2][4];
#pragma unroll
    for (int j = 0; j < C; j += 2) {
        float ra0, ra1, rb0, rb1;
        dot16x2(sp0, sp1, &sh_qkvw[j * C], ra0, ra1);
        dot16x2(sp0, sp1, &sh_qkvw[(j + 1) * C], rb0, rb1);
        qp0[j >> 3][(j & 7) >> 1] = pack2(ra0 + sh_qkvb[j], rb0 + sh_qkvb[j + 1]);
        qp1[j >> 3][(j & 7) >> 1] = pack2(ra1 + sh_qkvb[j], rb1 + sh_qkvb[j + 1]);
    }
#pragma unroll 2
    for (int j = 0; j < C; j += 2) {          // K
        float ra0, ra1, rb0, rb1;
        dot16x2(sp0, sp1, &sh_qkvw[(16 + j) * C], ra0, ra1);
        dot16x2(sp0, sp1, &sh_qkvw[(16 + j + 1) * C], rb0, rb1);
        int h = j >> 3, d = j & 7;
        float* base = &sh_k[((w * 2 + h) * 64 + lane) * 8 + d];
        *(float2*)base         = make_float2(ra0 + sh_qkvb[16 + j], rb0 + sh_qkvb[16 + j + 1]);
        *(float2*)(base + 256) = make_float2(ra1 + sh_qkvb[16 + j], rb1 + sh_qkvb[16 + j + 1]);
    }
#pragma unroll 2
    for (int j = 0; j < C; j += 2) {          // V
        float ra0, ra1, rb0, rb1;
        dot16x2(sp0, sp1, &sh_qkvw[(32 + j) * C], ra0, ra1);
        dot16x2(sp0, sp1, &sh_qkvw[(32 + j + 1) * C], rb0, rb1);
        int h = j >> 3, d = j & 7;
        float* base = &sh_v[((w * 2 + h) * 64 + lane) * 8 + d];
        *(float2*)base         = make_float2(ra0 + sh_qkvb[32 + j], rb0 + sh_qkvb[32 + j + 1]);
        *(float2*)(base + 256) = make_float2(ra1 + sh_qkvb[32 + j], rb1 + sh_qkvb[32 + j + 1]);
    }
    __syncwarp();   // K/V are warp-private (warp == window)

    // ---- window attention; logits already in log2 domain -> bare ex2 ----
    u64 aop0[8], aop1[8];
#pragma unroll
    for (int h = 0; h < HEADS; h++) {
        const ulonglong2* kb = (const ulonglong2*)&sh_k[(w * 2 + h) * 64 * 8];
        const ulonglong2* vb = (const ulonglong2*)&sh_v[(w * 2 + h) * 64 * 8];
        float sA0 = 0.f, sB0 = 0.f, sA1 = 0.f, sB1 = 0.f;
        u64 o0[4] = {0, 0, 0, 0}, o1[4] = {0, 0, 0, 0};
#pragma unroll 2
        for (int m = 0; m < NTOK; m++) {
            ulonglong2 ka = kb[2 * m], kc = kb[2 * m + 1];
            u64 d0a = 0, d0b = 0, d1a = 0, d1b = 0;
            ffma2(d0a, qp0[h][0], ka.x); ffma2(d0b, qp0[h][1], ka.y);
            ffma2(d0a, qp0[h][2], kc.x); ffma2(d0b, qp0[h][3], kc.y);
            ffma2(d1a, qp1[h][0], ka.x); ffma2(d1b, qp1[h][1], ka.y);
            ffma2(d1a, qp1[h][2], kc.x); ffma2(d1b, qp1[h][3], kc.y);
            float p0 = fexp2(hsum2(d0a, d0b));
            float p1 = fexp2(hsum2(d1a, d1b));
            if (m & 1) { sB0 += p0; sB1 += p1; }
            else       { sA0 += p0; sA1 += p1; }
            ulonglong2 va = vb[2 * m], vc = vb[2 * m + 1];
            u64 pp0 = pack2(p0, p0), pp1 = pack2(p1, p1);
            ffma2(o0[0], pp0, va.x); ffma2(o0[1], pp0, va.y);
            ffma2(o0[2], pp0, vc.x); ffma2(o0[3], pp0, vc.y);
            ffma2(o1[0], pp1, va.x); ffma2(o1[1], pp1, va.y);
            ffma2(o1[2], pp1, vc.x); ffma2(o1[3], pp1, vc.y);
        }
        float r0 = frcp(sA0 + sB0), r1 = frcp(sA1 + sB1);
        u64 rr0 = pack2(r0, r0), rr1 = pack2(r1, r1);
#pragma unroll
        for (int i = 0; i < 4; i++) {
            aop0[h * 4 + i] = fmul2(o0[i], rr0);
            aop1[h * 4 + i] = fmul2(o1[i], rr1);
        }
    }

    // ---- proj + residual -> x2 ----
    u64 x2p0[8], x2p1[8];
#pragma unroll
    for (int j = 0; j < C; j += 2) {
        float ra0, ra1, rb0, rb1;
        dot16x2(aop0, aop1, &sh_projw[j * C], ra0, ra1);
        dot16x2(aop0, aop1, &sh_projw[(j + 1) * C], rb0, rb1);
        float sa0, sa1, sb0, sb1;
        unpack2(sp0[j >> 1], sa0, sb0);
        unpack2(sp1[j >> 1], sa1, sb1);
        x2p0[j >> 1] = pack2(sa0 + ra0 + sh_projb[j], sb0 + rb0 + sh_projb[j + 1]);
        x2p1[j >> 1] = pack2(sa1 + ra1 + sh_projb[j], sb1 + rb1 + sh_projb[j + 1]);
    }

    // ---- MLP: fc1 (aff2 folded) -> GELU -> fc2 ----
    u64 fo0[8] = {0, 0, 0, 0, 0, 0, 0, 0}, fo1[8] = {0, 0, 0, 0, 0, 0, 0, 0};
#pragma unroll 2
    for (int j = 0; j < HID; j++) {
        float t0, t1;
        dot16x2(x2p0, x2p1, &sh_fc1w[j * C], t0, t1);
        t0 += sh_fc1b[j]; t1 += sh_fc1b[j];
        float u0 = 0.7978845608028654f * fmaf(0.044715f * t0, t0 * t0, t0);
        float u1 = 0.7978845608028654f * fmaf(0.044715f * t1, t1 * t1, t1);
        float g0 = 0.5f * t0 * (1.f + ftanh(u0));
        float g1 = 0.5f * t1 * (1.f + ftanh(u1));
        const ulonglong2* wp = (const ulonglong2*)&sh_fc2wt[j * C];
        ulonglong2 w0 = wp[0], w1 = wp[1], w2 = wp[2], w3 = wp[3];
        u64 gg0 = pack2(g0, g0), gg1 = pack2(g1, g1);
        ffma2(fo0[0], gg0, w0.x); ffma2(fo0[1], gg0, w0.y);
        ffma2(fo0[2], gg0, w1.x); ffma2(fo0[3], gg0, w1.y);
        ffma2(fo0[4], gg0, w2.x); ffma2(fo0[5], gg0, w2.y);
        ffma2(fo0[6], gg0, w3.x); ffma2(fo0[7], gg0, w3.y);
        ffma2(fo1[0], gg1, w0.x); ffma2(fo1[1], gg1, w0.y);
        ffma2(fo1[2], gg1, w1.x); ffma2(fo1[3], gg1, w1.y);
        ffma2(fo1[4], gg1, w2.x); ffma2(fo1[5], gg1, w2.y);
        ffma2(fo1[6], gg1, w3.x); ffma2(fo1[7], gg1, w3.y);
    }

    // ---- residual + NCHW write (2 tokens) ----
    float* ob = out + (size_t)b * C * HH * WW;
    const int gx = x0 + w * 8 + tx;
    const int gy0 = y0 + ty0, gy1 = y0 + ty0 + 4;
#pragma unroll
    for (int i = 0; i < 8; i++) {
        float lo0, hi0, lo1, hi1, xa0, xb0, xa1, xb1;
        unpack2(fo0[i], lo0, hi0); unpack2(fo1[i], lo1, hi1);
        unpack2(x2p0[i], xa0, xb0); unpack2(x2p1[i], xa1, xb1);
        int c0 = 2 * i;
        ob[c0 * (HH * WW) + gy0 * WW + gx]       = xa0 + sh_fc2b[c0]     + lo0;
        ob[(c0 + 1) * (HH * WW) + gy0 * WW + gx] = xb0 + sh_fc2b[c0 + 1] + hi0;
        ob[c0 * (HH * WW) + gy1 * WW + gx]       = xa1 + sh_fc2b[c0]     + lo1;
        ob[(c0 + 1) * (HH * WW) + gy1 * WW + gx] = xb1 + sh_fc2b[c0 + 1] + hi1;
    }
#undef HALO
}

extern "C" void kernel_launch(void* const* d_in, const int* in_sizes, int n_in,
                              void* d_out, int out_size) {
    (void)n_in; (void)out_size;
    const float* x      = (const float*)d_in[0];
    const float* pos_w  = (const float*)d_in[1];
    const float* pos_b  = (const float*)d_in[2];
    const float* alpha1 = (const float*)d_in[3];
    const float* beta1  = (const float*)d_in[4];
    const float* color1 = (const float*)d_in[5];
    const float* qkv_w  = (const float*)d_in[6];
    const float* qkv_b  = (const float*)d_in[7];
    const float* proj_w = (const float*)d_in[8];
    const float* proj_b = (const float*)d_in[9];
    const float* alpha2 = (const float*)d_in[10];
    const float* beta2  = (const float*)d_in[11];
    const float* color2 = (const float*)d_in[12];
    const float* fc1_w  = (const float*)d_in[13];
    const float* fc1_b  = (const float*)d_in[14];
    const float* fc2_w  = (const float*)d_in[15];
    const float* fc2_b  = (const float*)d_in[16];

    prep_kernel<<<1, 256>>>(alpha1, beta1, color1, qkv_w, qkv_b,
                            alpha2, beta2, color2, fc1_w, fc1_b, fc2_w);

    int B = in_sizes[0] / (C * HH * WW);
    dim3 grid(WW / (CTAW * WS), HH / WS, B);
    swin_fused_kernel<<<grid, NTHR>>>(
        x, pos_w, pos_b, proj_w, proj_b, fc2_b, (float*)d_out);
}